// round 11
// baseline (speedup 1.0000x reference)
#include <cuda_runtime.h>

// SoftQuantize: x (8192,512) fp32, c (4,256) fp32, sigma (1,) fp32 -> out (8192,512) fp32
// rows = 8192*128 subvectors of dim 4; softmax over 256 centers.
//
// Single pass, UNSHIFTED: arg'_l = k1*(z.c_l) + beta_l  (k1=2*s*log2e,
// beta_l=-s*log2e*||c_l||^2). The per-row softmax shift cancels in num/den, so
// it is omitted (pure 4-FMA dot chain seeded by beta -> shortest path to ex2).
// Guard: accept a row only if den in [1e-30, 1e36]; |num| <= max|k1*c|*den
// (~50x den) so accepted rows have finite numerators. den is a sum of
// non-negatives: ex2 overflow -> den=inf -> rejected; NaN fails the range test.
// Rejected rows (P ~ 2.5e-4) are recomputed exactly with a two-pass max.
//
// Row-pair f32x2 packing: each half-lane is a complete per-row value.
// c pre-scaled by k1 (cancels in ratio; undone by 1/k1 at the end).

#define LQ 256
#define TPB 128
#define G 4                 // rows per thread = 2 pairs
#define NROWS (8192*128)
#define DMIN 1e-30f
#define DMAX 1e36f

typedef unsigned long long u64;

static __device__ __forceinline__ u64 pk(float lo, float hi) {
    u64 r; asm("mov.b64 %0, {%1, %2};" : "=l"(r) : "f"(lo), "f"(hi)); return r;
}
static __device__ __forceinline__ void unpk(u64 v, float& lo, float& hi) {
    asm("mov.b64 {%0, %1}, %2;" : "=f"(lo), "=f"(hi) : "l"(v));
}
static __device__ __forceinline__ u64 f2fma(u64 a, u64 b, u64 c) {
    u64 d; asm("fma.rn.f32x2 %0, %1, %2, %3;" : "=l"(d) : "l"(a), "l"(b), "l"(c)); return d;
}
static __device__ __forceinline__ u64 f2add(u64 a, u64 b) {
    u64 d; asm("add.rn.f32x2 %0, %1, %2;" : "=l"(d) : "l"(a), "l"(b)); return d;
}
static __device__ __forceinline__ float ex2f(float x) {
    float y; asm("ex2.approx.f32 %0, %1;" : "=f"(y) : "f"(x)); return y;
}
static __device__ __forceinline__ float rcpf(float x) {
    float y; asm("rcp.approx.f32 %0, %1;" : "=f"(y) : "f"(x)); return y;
}

// Exact two-pass softmax for one row (rare tail fallback).
static __device__ __noinline__ void fb_row(const float4* __restrict__ x4,
                                           float4* __restrict__ out4,
                                           int row,
                                           const ulonglong2* scA,
                                           const ulonglong2* scB,
                                           const u64* sbb,
                                           float invk1)
{
    float4 z = x4[row];
    float m = -1.0e30f;
    for (int l = 0; l < LQ; ++l) {
        const float* fA = (const float*)&scA[l];   // [0]=k1*c0, [2]=k1*c1
        const float* fB = (const float*)&scB[l];   // [0]=k1*c2, [2]=k1*c3
        float beta = ((const float*)&sbb[l])[0];
        float arg = fmaf(z.x, fA[0], beta);
        arg = fmaf(z.y, fA[2], arg);
        arg = fmaf(z.z, fB[0], arg);
        arg = fmaf(z.w, fB[2], arg);
        m = fmaxf(m, arg);
    }
    float den = 0.f, n0 = 0.f, n1 = 0.f, n2 = 0.f, n3 = 0.f;
    for (int l = 0; l < LQ; ++l) {
        const float* fA = (const float*)&scA[l];
        const float* fB = (const float*)&scB[l];
        float beta = ((const float*)&sbb[l])[0];
        float arg = fmaf(z.x, fA[0], beta);
        arg = fmaf(z.y, fA[2], arg);
        arg = fmaf(z.z, fB[0], arg);
        arg = fmaf(z.w, fB[2], arg);
        float p = ex2f(arg - m);
        den += p;
        n0 = fmaf(p, fA[0], n0);
        n1 = fmaf(p, fA[2], n1);
        n2 = fmaf(p, fB[0], n2);
        n3 = fmaf(p, fB[2], n3);
    }
    float sf = rcpf(den) * invk1;
    out4[row] = make_float4(n0*sf, n1*sf, n2*sf, n3*sf);
}

__global__ __launch_bounds__(TPB, 8)
void softq_kernel(const float4* __restrict__ x4,
                  const float*  __restrict__ c,
                  const float*  __restrict__ sigma,
                  float4*       __restrict__ out4)
{
    __shared__ ulonglong2 scA[LQ];  // { pk(k1*c0,k1*c0), pk(k1*c1,k1*c1) }
    __shared__ ulonglong2 scB[LQ];  // { pk(k1*c2,k1*c2), pk(k1*c3,k1*c3) }
    __shared__ u64        sbb[LQ];  // pk(beta, beta)

    const float LOG2E = 1.4426950408889634f;
    float s  = fmaxf(sigma[0], 0.0f) + 1e-4f;
    float sl = s * LOG2E;
    float k1 = 2.0f * sl;

    int t = threadIdx.x;
    #pragma unroll
    for (int i = t; i < LQ; i += TPB) {
        float c0 = c[i], c1 = c[LQ + i], c2 = c[2*LQ + i], c3 = c[3*LQ + i];
        float csq  = c0*c0 + c1*c1 + c2*c2 + c3*c3;
        float beta = -sl * csq;
        scA[i].x = pk(k1*c0, k1*c0);
        scA[i].y = pk(k1*c1, k1*c1);
        scB[i].x = pk(k1*c2, k1*c2);
        scB[i].y = pk(k1*c3, k1*c3);
        sbb[i]   = pk(beta, beta);
    }
    __syncthreads();

    const int base = blockIdx.x * (TPB * G) + t;  // rows: base + g*TPB, g=0..3

    // zz[m][p]: component m of rows (2p, 2p+1) packed
    u64 zz[4][2];
    #pragma unroll
    for (int p = 0; p < 2; ++p) {
        float4 a = x4[base + (2*p    ) * TPB];
        float4 b = x4[base + (2*p + 1) * TPB];
        zz[0][p] = pk(a.x, b.x);
        zz[1][p] = pk(a.y, b.y);
        zz[2][p] = pk(a.z, b.z);
        zz[3][p] = pk(a.w, b.w);
    }

    u64 den2[2] = {0ull, 0ull};
    u64 nn[4][2];
    nn[0][0] = nn[1][0] = nn[2][0] = nn[3][0] = 0ull;
    nn[0][1] = nn[1][1] = nn[2][1] = nn[3][1] = 0ull;

    #pragma unroll 2
    for (int l = 0; l < LQ; ++l) {
        ulonglong2 cA = scA[l];
        ulonglong2 cB = scB[l];
        u64 bb = sbb[l];
        #pragma unroll
        for (int p = 0; p < 2; ++p) {
            u64 d = f2fma(zz[0][p], cA.x, bb);   // beta seeds the chain
            d     = f2fma(zz[1][p], cA.y, d);
            d     = f2fma(zz[2][p], cB.x, d);
            d     = f2fma(zz[3][p], cB.y, d);
            float aL, aH; unpk(d, aL, aH);
            u64 pp = pk(ex2f(aL), ex2f(aH));
            den2[p]  = f2add(den2[p], pp);
            nn[0][p] = f2fma(pp, cA.x, nn[0][p]);
            nn[1][p] = f2fma(pp, cA.y, nn[1][p]);
            nn[2][p] = f2fma(pp, cB.x, nn[2][p]);
            nn[3][p] = f2fma(pp, cB.y, nn[3][p]);
        }
    }

    // ---- epilogue: divide, undo k1 scaling; exact fallback for out-of-range den ----
    float invk1 = 1.0f / k1;
    #pragma unroll
    for (int p = 0; p < 2; ++p) {
        float dLo, dHi; unpk(den2[p], dLo, dHi);
        int rowA = base + (2*p    ) * TPB;
        int rowB = base + (2*p + 1) * TPB;
        bool okLo = (dLo >= DMIN) && (dLo <= DMAX);   // false for NaN/inf too
        bool okHi = (dHi >= DMIN) && (dHi <= DMAX);
        if (!okLo || !okHi) {
            fb_row(x4, out4, rowA, scA, scB, sbb, invk1);
            fb_row(x4, out4, rowB, scA, scB, sbb, invk1);
        } else {
            float sfLo = rcpf(dLo) * invk1;
            float sfHi = rcpf(dHi) * invk1;
            float n0l, n0h, n1l, n1h, n2l, n2h, n3l, n3h;
            unpk(nn[0][p], n0l, n0h);
            unpk(nn[1][p], n1l, n1h);
            unpk(nn[2][p], n2l, n2h);
            unpk(nn[3][p], n3l, n3h);
            out4[rowA] = make_float4(n0l*sfLo, n1l*sfLo, n2l*sfLo, n3l*sfLo);
            out4[rowB] = make_float4(n0h*sfHi, n1h*sfHi, n2h*sfHi, n3h*sfHi);
        }
    }
}

extern "C" void kernel_launch(void* const* d_in, const int* in_sizes, int n_in,
                              void* d_out, int out_size)
{
    const float* x     = (const float*)d_in[0];
    const float* c     = (const float*)d_in[1];
    const float* sigma = (const float*)d_in[2];
    float* out = (float*)d_out;

    int blocks = NROWS / (TPB * G);   // 2048
    softq_kernel<<<blocks, TPB>>>((const float4*)x, c, sigma, (float4*)out);
}

// round 12
// speedup vs baseline: 1.2009x; 1.2009x over previous
#include <cuda_runtime.h>

// SoftQuantize: x (8192,512) fp32, c (4,256) fp32, sigma (1,) fp32 -> out (8192,512) fp32
// rows = 8192*128 subvectors of dim 4; softmax over 256 centers.
//
// CENTER-PAIR f32x2 packing, ONE ROW PER THREAD (minimal register state ->
// high occupancy to absorb MUFU/FMA queue jitter on in-order warps):
//   lanes of each f32x2 = centers (2j, 2j+1) for this thread's row.
//   den / numerators are packed even/odd-center partial sums, combined at end.
//
// Unshifted args: arg_l = k1*(z.c_l) + beta_l  (k1=2*s*log2e,
// beta_l = -s*log2e*||c_l||^2); the per-row softmax shift cancels in num/den.
// Guard: accept a row only if total den in [1e-30, 1e36]  (|num| <= ~50*den,
// so accepted numerators are finite; den is a sum of non-negatives, so ex2
// overflow -> den=inf -> rejected; NaN fails the range test). Rejected rows
// (P ~ 2.5e-4) are recomputed exactly with a scalar two-pass max fallback.
//
// c pre-scaled by k1 (cancels in ratio; undone by 1/k1 at the end).

#define LQ  256
#define NP  128             // center pairs
#define TPB 128
#define NROWS (8192*128)
#define DMIN 1e-30f
#define DMAX 1e36f

typedef unsigned long long u64;

static __device__ __forceinline__ u64 pk(float lo, float hi) {
    u64 r; asm("mov.b64 %0, {%1, %2};" : "=l"(r) : "f"(lo), "f"(hi)); return r;
}
static __device__ __forceinline__ void unpk(u64 v, float& lo, float& hi) {
    asm("mov.b64 {%0, %1}, %2;" : "=f"(lo), "=f"(hi) : "l"(v));
}
static __device__ __forceinline__ u64 f2fma(u64 a, u64 b, u64 c) {
    u64 d; asm("fma.rn.f32x2 %0, %1, %2, %3;" : "=l"(d) : "l"(a), "l"(b), "l"(c)); return d;
}
static __device__ __forceinline__ u64 f2add(u64 a, u64 b) {
    u64 d; asm("add.rn.f32x2 %0, %1, %2;" : "=l"(d) : "l"(a), "l"(b)); return d;
}
static __device__ __forceinline__ float ex2f(float x) {
    float y; asm("ex2.approx.f32 %0, %1;" : "=f"(y) : "f"(x)); return y;
}
static __device__ __forceinline__ float rcpf(float x) {
    float y; asm("rcp.approx.f32 %0, %1;" : "=f"(y) : "f"(x)); return y;
}

// Exact two-pass softmax for one row (rare tail fallback).
// scA[j] = { pk(k1c0[2j],k1c0[2j+1]), pk(k1c1[2j],k1c1[2j+1]) }
// scB[j] = { pk(k1c2...),             pk(k1c3...) },  sbb[j] = pk(b[2j],b[2j+1])
static __device__ __noinline__ void fb_row(const float4* __restrict__ x4,
                                           float4* __restrict__ out4,
                                           int row,
                                           const ulonglong2* scA,
                                           const ulonglong2* scB,
                                           const u64* sbb,
                                           float invk1)
{
    float4 z = x4[row];
    float m = -1.0e30f;
    for (int j = 0; j < NP; ++j) {
        const float* fA = (const float*)&scA[j];   // [0],[1]=c0 pair; [2],[3]=c1 pair
        const float* fB = (const float*)&scB[j];   // [0],[1]=c2 pair; [2],[3]=c3 pair
        const float* fb = (const float*)&sbb[j];
        #pragma unroll
        for (int h = 0; h < 2; ++h) {
            float arg = fmaf(z.x, fA[h], fb[h]);
            arg = fmaf(z.y, fA[2 + h], arg);
            arg = fmaf(z.z, fB[h], arg);
            arg = fmaf(z.w, fB[2 + h], arg);
            m = fmaxf(m, arg);
        }
    }
    float den = 0.f, n0 = 0.f, n1 = 0.f, n2 = 0.f, n3 = 0.f;
    for (int j = 0; j < NP; ++j) {
        const float* fA = (const float*)&scA[j];
        const float* fB = (const float*)&scB[j];
        const float* fb = (const float*)&sbb[j];
        #pragma unroll
        for (int h = 0; h < 2; ++h) {
            float arg = fmaf(z.x, fA[h], fb[h]);
            arg = fmaf(z.y, fA[2 + h], arg);
            arg = fmaf(z.z, fB[h], arg);
            arg = fmaf(z.w, fB[2 + h], arg);
            float p = ex2f(arg - m);
            den += p;
            n0 = fmaf(p, fA[h], n0);
            n1 = fmaf(p, fA[2 + h], n1);
            n2 = fmaf(p, fB[h], n2);
            n3 = fmaf(p, fB[2 + h], n3);
        }
    }
    float sf = rcpf(den) * invk1;
    out4[row] = make_float4(n0*sf, n1*sf, n2*sf, n3*sf);
}

__global__ __launch_bounds__(TPB, 10)
void softq_kernel(const float4* __restrict__ x4,
                  const float*  __restrict__ c,
                  const float*  __restrict__ sigma,
                  float4*       __restrict__ out4)
{
    __shared__ ulonglong2 scA[NP];  // { pk(k1c0 pair), pk(k1c1 pair) }
    __shared__ ulonglong2 scB[NP];  // { pk(k1c2 pair), pk(k1c3 pair) }
    __shared__ u64        sbb[NP];  // pk(beta pair)

    const float LOG2E = 1.4426950408889634f;
    float s  = fmaxf(sigma[0], 0.0f) + 1e-4f;
    float sl = s * LOG2E;
    float k1 = 2.0f * sl;

    int t = threadIdx.x;            // t == pair index j for setup (TPB == NP)
    {
        int l0 = 2*t, l1 = 2*t + 1;
        float a0 = c[l0],        a1 = c[l1];
        float b0 = c[LQ + l0],   b1 = c[LQ + l1];
        float c0 = c[2*LQ + l0], c1 = c[2*LQ + l1];
        float d0 = c[3*LQ + l0], d1 = c[3*LQ + l1];
        float q0 = a0*a0 + b0*b0 + c0*c0 + d0*d0;
        float q1 = a1*a1 + b1*b1 + c1*c1 + d1*d1;
        scA[t].x = pk(k1*a0, k1*a1);
        scA[t].y = pk(k1*b0, k1*b1);
        scB[t].x = pk(k1*c0, k1*c1);
        scB[t].y = pk(k1*d0, k1*d1);
        sbb[t]   = pk(-sl*q0, -sl*q1);
    }
    __syncthreads();

    const int row = blockIdx.x * TPB + t;

    // zz[m] = pk(z_m, z_m): row components duplicated across the f32x2 lanes
    u64 zz0, zz1, zz2, zz3;
    {
        float4 z = x4[row];
        zz0 = pk(z.x, z.x);
        zz1 = pk(z.y, z.y);
        zz2 = pk(z.z, z.z);
        zz3 = pk(z.w, z.w);
    }

    u64 den2 = 0ull;
    u64 nn0 = 0ull, nn1 = 0ull, nn2 = 0ull, nn3 = 0ull;

    #pragma unroll 4
    for (int j = 0; j < NP; ++j) {
        ulonglong2 cA = scA[j];
        ulonglong2 cB = scB[j];
        u64 bb = sbb[j];
        u64 d = f2fma(zz0, cA.x, bb);    // beta pair seeds the chain
        d     = f2fma(zz1, cA.y, d);
        d     = f2fma(zz2, cB.x, d);
        d     = f2fma(zz3, cB.y, d);
        float aL, aH; unpk(d, aL, aH);
        u64 pp = pk(ex2f(aL), ex2f(aH));
        den2 = f2add(den2, pp);
        nn0  = f2fma(pp, cA.x, nn0);
        nn1  = f2fma(pp, cA.y, nn1);
        nn2  = f2fma(pp, cB.x, nn2);
        nn3  = f2fma(pp, cB.y, nn3);
    }

    // ---- horizontal combine (even+odd centers), guard, divide ----
    float invk1 = 1.0f / k1;
    float dL, dH; unpk(den2, dL, dH);
    float den = dL + dH;
    bool ok = (den >= DMIN) && (den <= DMAX);   // false for NaN/inf too
    if (!ok) {
        fb_row(x4, out4, row, scA, scB, sbb, invk1);
    } else {
        float sf = rcpf(den) * invk1;
        float n0l, n0h, n1l, n1h, n2l, n2h, n3l, n3h;
        unpk(nn0, n0l, n0h);
        unpk(nn1, n1l, n1h);
        unpk(nn2, n2l, n2h);
        unpk(nn3, n3l, n3h);
        out4[row] = make_float4((n0l + n0h) * sf,
                                (n1l + n1h) * sf,
                                (n2l + n2h) * sf,
                                (n3l + n3h) * sf);
    }
}

extern "C" void kernel_launch(void* const* d_in, const int* in_sizes, int n_in,
                              void* d_out, int out_size)
{
    const float* x     = (const float*)d_in[0];
    const float* c     = (const float*)d_in[1];
    const float* sigma = (const float*)d_in[2];
    float* out = (float*)d_out;

    int blocks = NROWS / TPB;   // 8192
    softq_kernel<<<blocks, TPB>>>((const float4*)x, c, sigma, (float4*)out);
}

// round 13
// speedup vs baseline: 1.2639x; 1.0525x over previous
#include <cuda_runtime.h>

// SoftQuantize: x (8192,512) fp32, c (4,256) fp32, sigma (1,) fp32 -> out (8192,512) fp32
// rows = 8192*128 subvectors of dim 4; softmax over 256 centers.
//
// CENTER-PAIR f32x2 packing, TWO ROWS PER THREAD:
//   f32x2 lanes = centers (2j, 2j+1); den/numerators are even/odd-center
//   partial sums, combined horizontally at the end. Two independent
//   dot->ex2->accumulate chains per iteration (ILP) share one set of
//   broadcast codebook LDS loads (halves L1 traffic vs one row/thread).
//
// Unshifted args: arg_l = k1*(z.c_l) + beta_l  (k1=2*s*log2e,
// beta_l = -s*log2e*||c_l||^2); the per-row softmax shift cancels in num/den.
// Guard: accept a row only if total den in [1e-30, 1e36]  (|num| <= ~50*den,
// so accepted numerators are finite; den is a sum of non-negatives, so ex2
// overflow -> den=inf -> rejected; NaN fails the range test). Rejected rows
// (P ~ 2.5e-4) are recomputed exactly with a scalar two-pass max fallback.
//
// c pre-scaled by k1 (cancels in ratio; undone by 1/k1 at the end).

#define LQ  256
#define NP  128             // center pairs
#define TPB 128
#define NROWS (8192*128)
#define DMIN 1e-30f
#define DMAX 1e36f

typedef unsigned long long u64;

static __device__ __forceinline__ u64 pk(float lo, float hi) {
    u64 r; asm("mov.b64 %0, {%1, %2};" : "=l"(r) : "f"(lo), "f"(hi)); return r;
}
static __device__ __forceinline__ void unpk(u64 v, float& lo, float& hi) {
    asm("mov.b64 {%0, %1}, %2;" : "=f"(lo), "=f"(hi) : "l"(v));
}
static __device__ __forceinline__ u64 f2fma(u64 a, u64 b, u64 c) {
    u64 d; asm("fma.rn.f32x2 %0, %1, %2, %3;" : "=l"(d) : "l"(a), "l"(b), "l"(c)); return d;
}
static __device__ __forceinline__ u64 f2add(u64 a, u64 b) {
    u64 d; asm("add.rn.f32x2 %0, %1, %2;" : "=l"(d) : "l"(a), "l"(b)); return d;
}
static __device__ __forceinline__ float ex2f(float x) {
    float y; asm("ex2.approx.f32 %0, %1;" : "=f"(y) : "f"(x)); return y;
}
static __device__ __forceinline__ float rcpf(float x) {
    float y; asm("rcp.approx.f32 %0, %1;" : "=f"(y) : "f"(x)); return y;
}

// Exact two-pass softmax for one row (rare tail fallback).
// scA[j] = { pk(k1c0[2j],k1c0[2j+1]), pk(k1c1[2j],k1c1[2j+1]) }
// scB[j] = { pk(k1c2...),             pk(k1c3...) },  sbb[j] = pk(b[2j],b[2j+1])
static __device__ __noinline__ void fb_row(const float4* __restrict__ x4,
                                           float4* __restrict__ out4,
                                           int row,
                                           const ulonglong2* scA,
                                           const ulonglong2* scB,
                                           const u64* sbb,
                                           float invk1)
{
    float4 z = x4[row];
    float m = -1.0e30f;
    for (int j = 0; j < NP; ++j) {
        const float* fA = (const float*)&scA[j];   // [0],[1]=c0 pair; [2],[3]=c1 pair
        const float* fB = (const float*)&scB[j];   // [0],[1]=c2 pair; [2],[3]=c3 pair
        const float* fb = (const float*)&sbb[j];
        #pragma unroll
        for (int h = 0; h < 2; ++h) {
            float arg = fmaf(z.x, fA[h], fb[h]);
            arg = fmaf(z.y, fA[2 + h], arg);
            arg = fmaf(z.z, fB[h], arg);
            arg = fmaf(z.w, fB[2 + h], arg);
            m = fmaxf(m, arg);
        }
    }
    float den = 0.f, n0 = 0.f, n1 = 0.f, n2 = 0.f, n3 = 0.f;
    for (int j = 0; j < NP; ++j) {
        const float* fA = (const float*)&scA[j];
        const float* fB = (const float*)&scB[j];
        const float* fb = (const float*)&sbb[j];
        #pragma unroll
        for (int h = 0; h < 2; ++h) {
            float arg = fmaf(z.x, fA[h], fb[h]);
            arg = fmaf(z.y, fA[2 + h], arg);
            arg = fmaf(z.z, fB[h], arg);
            arg = fmaf(z.w, fB[2 + h], arg);
            float p = ex2f(arg - m);
            den += p;
            n0 = fmaf(p, fA[h], n0);
            n1 = fmaf(p, fA[2 + h], n1);
            n2 = fmaf(p, fB[h], n2);
            n3 = fmaf(p, fB[2 + h], n3);
        }
    }
    float sf = rcpf(den) * invk1;
    out4[row] = make_float4(n0*sf, n1*sf, n2*sf, n3*sf);
}

__global__ __launch_bounds__(TPB, 8)
void softq_kernel(const float4* __restrict__ x4,
                  const float*  __restrict__ c,
                  const float*  __restrict__ sigma,
                  float4*       __restrict__ out4)
{
    __shared__ ulonglong2 scA[NP];  // { pk(k1c0 pair), pk(k1c1 pair) }
    __shared__ ulonglong2 scB[NP];  // { pk(k1c2 pair), pk(k1c3 pair) }
    __shared__ u64        sbb[NP];  // pk(beta pair)

    const float LOG2E = 1.4426950408889634f;
    float s  = fmaxf(sigma[0], 0.0f) + 1e-4f;
    float sl = s * LOG2E;
    float k1 = 2.0f * sl;

    int t = threadIdx.x;            // t == pair index j for setup (TPB == NP)
    {
        int l0 = 2*t, l1 = 2*t + 1;
        float a0 = c[l0],        a1 = c[l1];
        float b0 = c[LQ + l0],   b1 = c[LQ + l1];
        float c0 = c[2*LQ + l0], c1 = c[2*LQ + l1];
        float d0 = c[3*LQ + l0], d1 = c[3*LQ + l1];
        float q0 = a0*a0 + b0*b0 + c0*c0 + d0*d0;
        float q1 = a1*a1 + b1*b1 + c1*c1 + d1*d1;
        scA[t].x = pk(k1*a0, k1*a1);
        scA[t].y = pk(k1*b0, k1*b1);
        scB[t].x = pk(k1*c0, k1*c1);
        scB[t].y = pk(k1*d0, k1*d1);
        sbb[t]   = pk(-sl*q0, -sl*q1);
    }
    __syncthreads();

    const int rowA = blockIdx.x * (2 * TPB) + t;   // two rows per thread
    const int rowB = rowA + TPB;

    // zz?[m] = pk(z_m, z_m): row components duplicated across the f32x2 lanes
    u64 zA0, zA1, zA2, zA3, zB0, zB1, zB2, zB3;
    {
        float4 za = x4[rowA];
        float4 zb = x4[rowB];
        zA0 = pk(za.x, za.x); zA1 = pk(za.y, za.y);
        zA2 = pk(za.z, za.z); zA3 = pk(za.w, za.w);
        zB0 = pk(zb.x, zb.x); zB1 = pk(zb.y, zb.y);
        zB2 = pk(zb.z, zb.z); zB3 = pk(zb.w, zb.w);
    }

    u64 denA = 0ull, nA0 = 0ull, nA1 = 0ull, nA2 = 0ull, nA3 = 0ull;
    u64 denB = 0ull, nB0 = 0ull, nB1 = 0ull, nB2 = 0ull, nB3 = 0ull;

    #pragma unroll 2
    for (int j = 0; j < NP; ++j) {
        ulonglong2 cA = scA[j];
        ulonglong2 cB = scB[j];
        u64 bb = sbb[j];

        // two independent chains share the codebook registers
        u64 dA = f2fma(zA0, cA.x, bb);
        u64 dB = f2fma(zB0, cA.x, bb);
        dA     = f2fma(zA1, cA.y, dA);
        dB     = f2fma(zB1, cA.y, dB);
        dA     = f2fma(zA2, cB.x, dA);
        dB     = f2fma(zB2, cB.x, dB);
        dA     = f2fma(zA3, cB.y, dA);
        dB     = f2fma(zB3, cB.y, dB);

        float aL, aH, bL, bH;
        unpk(dA, aL, aH);
        unpk(dB, bL, bH);
        u64 ppA = pk(ex2f(aL), ex2f(aH));
        u64 ppB = pk(ex2f(bL), ex2f(bH));

        denA = f2add(denA, ppA);
        denB = f2add(denB, ppB);
        nA0  = f2fma(ppA, cA.x, nA0);
        nB0  = f2fma(ppB, cA.x, nB0);
        nA1  = f2fma(ppA, cA.y, nA1);
        nB1  = f2fma(ppB, cA.y, nB1);
        nA2  = f2fma(ppA, cB.x, nA2);
        nB2  = f2fma(ppB, cB.x, nB2);
        nA3  = f2fma(ppA, cB.y, nA3);
        nB3  = f2fma(ppB, cB.y, nB3);
    }

    // ---- horizontal combine (even+odd centers), guard, divide ----
    float invk1 = 1.0f / k1;
    {
        float dL, dH; unpk(denA, dL, dH);
        float den = dL + dH;
        if (!((den >= DMIN) && (den <= DMAX))) {       // NaN/inf fail too
            fb_row(x4, out4, rowA, scA, scB, sbb, invk1);
        } else {
            float sf = rcpf(den) * invk1;
            float n0l, n0h, n1l, n1h, n2l, n2h, n3l, n3h;
            unpk(nA0, n0l, n0h);
            unpk(nA1, n1l, n1h);
            unpk(nA2, n2l, n2h);
            unpk(nA3, n3l, n3h);
            out4[rowA] = make_float4((n0l + n0h) * sf, (n1l + n1h) * sf,
                                     (n2l + n2h) * sf, (n3l + n3h) * sf);
        }
    }
    {
        float dL, dH; unpk(denB, dL, dH);
        float den = dL + dH;
        if (!((den >= DMIN) && (den <= DMAX))) {
            fb_row(x4, out4, rowB, scA, scB, sbb, invk1);
        } else {
            float sf = rcpf(den) * invk1;
            float n0l, n0h, n1l, n1h, n2l, n2h, n3l, n3h;
            unpk(nB0, n0l, n0h);
            unpk(nB1, n1l, n1h);
            unpk(nB2, n2l, n2h);
            unpk(nB3, n3l, n3h);
            out4[rowB] = make_float4((n0l + n0h) * sf, (n1l + n1h) * sf,
                                     (n2l + n2h) * sf, (n3l + n3h) * sf);
        }
    }
}

extern "C" void kernel_launch(void* const* d_in, const int* in_sizes, int n_in,
                              void* d_out, int out_size)
{
    const float* x     = (const float*)d_in[0];
    const float* c     = (const float*)d_in[1];
    const float* sigma = (const float*)d_in[2];
    float* out = (float*)d_out;

    int blocks = NROWS / (2 * TPB);   // 4096
    softq_kernel<<<blocks, TPB>>>((const float4*)x, c, sigma, (float4*)out);
}